// round 7
// baseline (speedup 1.0000x reference)
#include <cuda_runtime.h>
#include <cstdint>

// RandomRoll: out[b,c,h,w] = x[b,c,(h - sh) & 511, (w - sw) & 511]
// x: [64, 3, 512, 512] fp32; shifts: [64, 2] int32.
// R5: ONE full 512-float row per warp, minimal regs -> max occupancy.
//   lane loads vecs (v0 + lane + 32k) & 127, k=0..3 (whole source row in warp)
//   circular realign closes in-warp (lane 0 contributes A[k+1] to the shfl)
//   streaming stores (st.global.cs): output is write-once, keep L2 for reads.

static constexpr int HMASK = 511;
static constexpr int WMASK = 511;
static constexpr int TPB   = 256;
static constexpr unsigned FULL = 0xffffffffu;

__device__ __forceinline__ void store_cs(float4* p, float4 v)
{
    asm volatile("st.global.cs.v4.f32 [%0], {%1, %2, %3, %4};"
                 :: "l"(p), "f"(v.x), "f"(v.y), "f"(v.z), "f"(v.w) : "memory");
}

// Realign output vec (lane + 32K) from the in-register source row A[0..3].
// off is warp-uniform (0..3). Neighbor of A[K]@lane is A[K]@lane+1, except
// lane 31 whose neighbor is A[(K+1)&3]@lane0 (contributed by lane 0).
template<int K>
__device__ __forceinline__ float4 realign(const float4 A[4], int off, int lane)
{
    float4 a = A[K];
    if (off == 0) return a;
    const float4 an = A[(K + 1) & 3];
    int src = (lane + 1) & 31;
    float4 B;
    B.x = __shfl_sync(FULL, (lane == 0) ? an.x : a.x, src);
    B.y = __shfl_sync(FULL, (lane == 0) ? an.y : a.y, src);
    B.z = __shfl_sync(FULL, (lane == 0) ? an.z : a.z, src);
    B.w = __shfl_sync(FULL, (lane == 0) ? an.w : a.w, src);
    if (off == 1) return make_float4(a.y, a.z, a.w, B.x);
    if (off == 2) return make_float4(a.z, a.w, B.x, B.y);
    return make_float4(a.w, B.x, B.y, B.z);
}

__global__ void __launch_bounds__(TPB)
random_roll_rows(const float4* __restrict__ x4,
                 const int*    __restrict__ shifts,
                 float4*       __restrict__ out4,
                 int n_rows)   // rows = (b*3+c)*512 + h; 128 float4 each
{
    int lane = threadIdx.x & 31;
    int row  = blockIdx.x * (TPB / 32) + (threadIdx.x >> 5);
    if (row >= n_rows) return;

    int h  = row & HMASK;
    int bc = row >> 9;
    int b  = bc / 3;

    int sh = __ldg(&shifts[2 * b]);
    int sw = __ldg(&shifts[2 * b + 1]);

    const float4* src = x4 + ((size_t)((bc << 9) | ((h - sh) & HMASK)) << 7);
    int s0  = (-sw) & WMASK;        // first source float of the rolled row
    int off = s0 & 3;               // intra-vec misalignment, warp-uniform
    int v0  = s0 >> 2;

    // All 4 aligned LDG.128 back-to-back (entire source row lands in the warp).
    float4 A[4];
    #pragma unroll
    for (int k = 0; k < 4; k++) A[k] = src[(v0 + lane + 32 * k) & 127];

    // Realign + streaming stores (aligned, fully coalesced per k).
    float4* o = out4 + ((size_t)row << 7) + lane;
    store_cs(o +  0, realign<0>(A, off, lane));
    store_cs(o + 32, realign<1>(A, off, lane));
    store_cs(o + 64, realign<2>(A, off, lane));
    store_cs(o + 96, realign<3>(A, off, lane));
}

// Scalar tail (defensive; these shapes divide into whole rows).
__global__ void random_roll_tail(const float* __restrict__ x,
                                 const int*   __restrict__ shifts,
                                 float*       __restrict__ out,
                                 int start, int total)
{
    int i = start + blockIdx.x * blockDim.x + threadIdx.x;
    if (i >= total) return;
    int w   = i & WMASK;
    int row = i >> 9;
    int h   = row & HMASK;
    int bc  = row >> 9;
    int b   = bc / 3;
    int sh = shifts[2 * b];
    int sw = shifts[2 * b + 1];
    out[i] = x[(((size_t)((bc << 9) | ((h - sh) & HMASK))) << 9) + ((w - sw) & WMASK)];
}

extern "C" void kernel_launch(void* const* d_in, const int* in_sizes, int n_in,
                              void* d_out, int out_size)
{
    const float4* x4     = (const float4*)d_in[0];
    const int*    shifts = (const int*)d_in[1];
    float4*       out4   = (float4*)d_out;

    int n_rows = out_size >> 9;                      // whole 512-float rows
    if (n_rows > 0) {
        int wpb    = TPB / 32;                       // 8 rows per block
        int blocks = (n_rows + wpb - 1) / wpb;
        random_roll_rows<<<blocks, TPB>>>(x4, shifts, out4, n_rows);
    }
    int tail_start = n_rows << 9;
    int tail = out_size - tail_start;
    if (tail > 0) {
        random_roll_tail<<<(tail + 255) / 256, 256>>>((const float*)d_in[0], shifts,
                                                      (float*)d_out, tail_start, out_size);
    }
}

// round 8
// speedup vs baseline: 1.0035x; 1.0035x over previous
#include <cuda_runtime.h>
#include <cstdint>

// RandomRoll: out[b,c,h,w] = x[b,c,(h - sh) & 511, (w - sw) & 511]
// x: [64, 3, 512, 512] fp32; shifts: [64, 2] int32.
// R8: 256-bit global accesses (Blackwell ld/st.global.v8.f32).
// One 512-float row per warp: lane owns vec8 slots (v0+lane) and (v0+lane+32)
// of the rotated source window (mod 64); wrap closes inside the warp.
// Realign by off = s0 & 7 via warp shuffle + uniform switch. Plain stores.

static constexpr int HMASK = 511;
static constexpr int WMASK = 511;
static constexpr int TPB   = 256;
static constexpr unsigned FULL = 0xffffffffu;

__device__ __forceinline__ void ldg256(float r[8], const float* p)
{
    asm volatile("ld.global.v8.f32 {%0,%1,%2,%3,%4,%5,%6,%7}, [%8];"
                 : "=f"(r[0]), "=f"(r[1]), "=f"(r[2]), "=f"(r[3]),
                   "=f"(r[4]), "=f"(r[5]), "=f"(r[6]), "=f"(r[7])
                 : "l"(p));
}

__device__ __forceinline__ void stg256(float* p, const float r[8])
{
    asm volatile("st.global.v8.f32 [%0], {%1,%2,%3,%4,%5,%6,%7,%8};"
                 :: "l"(p),
                    "f"(r[0]), "f"(r[1]), "f"(r[2]), "f"(r[3]),
                    "f"(r[4]), "f"(r[5]), "f"(r[6]), "f"(r[7])
                 : "memory");
}

template<int OFF>
__device__ __forceinline__ void sel8(const float a[8], const float B[8], float o[8])
{
    #pragma unroll
    for (int i = 0; i < 8; i++)
        o[i] = (i + OFF < 8) ? a[i + OFF] : B[i + OFF - 8];
}

__global__ void __launch_bounds__(TPB)
random_roll_rows(const float* __restrict__ x,
                 const int*   __restrict__ shifts,
                 float*       __restrict__ out,
                 int n_rows)   // rows = (b*3+c)*512 + h; 512 floats each
{
    int lane = threadIdx.x & 31;
    int row  = blockIdx.x * (TPB / 32) + (threadIdx.x >> 5);
    if (row >= n_rows) return;

    int h  = row & HMASK;
    int bc = row >> 9;
    int b  = bc / 3;

    int sh = __ldg(&shifts[2 * b]);
    int sw = __ldg(&shifts[2 * b + 1]);

    const float* src = x + ((size_t)((bc << 9) | ((h - sh) & HMASK)) << 9);
    int s0  = (-sw) & WMASK;       // first source float of the rolled row
    int off = s0 & 7;              // intra-vec8 misalignment, warp-uniform
    int v0  = s0 >> 3;             // first aligned source vec8 (row has 64)

    // Two aligned 256-bit loads: the entire source row lands in the warp.
    float A[2][8];
    ldg256(A[0], src + (((v0 + lane)      & 63) << 3));
    ldg256(A[1], src + (((v0 + lane + 32) & 63) << 3));

    float* o = out + ((size_t)row << 9) + (lane << 3);

    if (off == 0) {
        stg256(o,       A[0]);
        stg256(o + 256, A[1]);
        return;
    }

    // Neighbor vec8 of A[k]@lane is A[k]@(lane+1); lane 31 wraps to A[k^1]@lane0.
    float B0[8], B1[8];
    int srcl = (lane + 1) & 31;
    #pragma unroll
    for (int i = 0; i < 8; i++) {
        B0[i] = __shfl_sync(FULL, (lane == 0) ? A[1][i] : A[0][i], srcl);
        B1[i] = __shfl_sync(FULL, (lane == 0) ? A[0][i] : A[1][i], srcl);
    }

    float O0[8], O1[8];
    switch (off) {   // warp-uniform
        case 1: sel8<1>(A[0], B0, O0); sel8<1>(A[1], B1, O1); break;
        case 2: sel8<2>(A[0], B0, O0); sel8<2>(A[1], B1, O1); break;
        case 3: sel8<3>(A[0], B0, O0); sel8<3>(A[1], B1, O1); break;
        case 4: sel8<4>(A[0], B0, O0); sel8<4>(A[1], B1, O1); break;
        case 5: sel8<5>(A[0], B0, O0); sel8<5>(A[1], B1, O1); break;
        case 6: sel8<6>(A[0], B0, O0); sel8<6>(A[1], B1, O1); break;
        default: sel8<7>(A[0], B0, O0); sel8<7>(A[1], B1, O1); break;
    }
    stg256(o,       O0);
    stg256(o + 256, O1);
}

// Scalar tail (defensive; these shapes divide into whole rows).
__global__ void random_roll_tail(const float* __restrict__ x,
                                 const int*   __restrict__ shifts,
                                 float*       __restrict__ out,
                                 int start, int total)
{
    int i = start + blockIdx.x * blockDim.x + threadIdx.x;
    if (i >= total) return;
    int w   = i & WMASK;
    int row = i >> 9;
    int h   = row & HMASK;
    int bc  = row >> 9;
    int b   = bc / 3;
    int sh = shifts[2 * b];
    int sw = shifts[2 * b + 1];
    out[i] = x[(((size_t)((bc << 9) | ((h - sh) & HMASK))) << 9) + ((w - sw) & WMASK)];
}

extern "C" void kernel_launch(void* const* d_in, const int* in_sizes, int n_in,
                              void* d_out, int out_size)
{
    const float* x      = (const float*)d_in[0];
    const int*   shifts = (const int*)d_in[1];
    float*       out    = (float*)d_out;

    int n_rows = out_size >> 9;                      // whole 512-float rows
    if (n_rows > 0) {
        int wpb    = TPB / 32;                       // 8 rows per block
        int blocks = (n_rows + wpb - 1) / wpb;
        random_roll_rows<<<blocks, TPB>>>(x, shifts, out, n_rows);
    }
    int tail_start = n_rows << 9;
    int tail = out_size - tail_start;
    if (tail > 0) {
        random_roll_tail<<<(tail + 255) / 256, 256>>>(x, shifts, out, tail_start, out_size);
    }
}